// round 5
// baseline (speedup 1.0000x reference)
#include <cuda_runtime.h>
#include <math.h>

#define HH 512
#define WW 512
#define HW (512*512)
#define NORG 10
#define SS 32
#define NPART 64
#define NB 296                  // 2 blocks/SM on 148 SMs -> guaranteed co-resident

// Output layout (flattened reference tuple, fp32):
#define SIZE_BASE 0
#define CEN_BASE  (2*HW)
#define FIN_BASE  (2*HW + 2*NORG)   // *4 bytes = 16B aligned (80 % 16 == 0)

// Phase-A tile map: tile = 4096 floats (16 KB)
#define T_ARG  640                      // 10 organs x 64 chunks of heat
#define T_SIZE 128                      // 2*HW / 4096
#define T_ZERO 640                      // 10*HW / 4096
#define T_TOTAL (T_ARG + T_SIZE + T_ZERO)

// ---- scratch (no allocations allowed) ----
__device__ float g_pval[T_ARG];
__device__ int   g_pidx[T_ARG];
__device__ int4  g_box[NORG];           // (r0, c0, sh, sw)
__device__ int   g_idx[NORG];
__device__ unsigned g_arrive = 0;
__device__ unsigned g_release = 0;      // epoch counter (monotonic across replays)

__device__ __forceinline__ void better(float v, int i, float& bv, int& bi) {
    if (v > bv || (v == bv && i < bi)) { bv = v; bi = i; }
}
__device__ __forceinline__ float sigmoidf_(float x) {
    return 1.0f / (1.0f + __expf(-x));
}

__global__ void __launch_bounds__(256, 2)
fused_all(const float* __restrict__ f, float* __restrict__ out) {
    const int tid = threadIdx.x;
    const int bid = blockIdx.x;

    __shared__ unsigned s_snap;
    __shared__ int      s_last;
    __shared__ float    s_shape[SS*SS];
    __shared__ float    s_av[8];
    __shared__ int      s_ai[8];

    if (tid == 0) s_snap = *(volatile unsigned*)&g_release;   // epoch before this run's release
    __syncthreads();

    // ================= Phase A: argmax partials + size map + zero-fill =================
    for (int t = bid; t < T_TOTAL; t += NB) {
        if (t < T_ARG) {
            // ---- argmax partial over one 4096-float chunk of heat ----
            int o = t >> 6;
            int b = t & 63;
            const float4* heat = (const float4*)(f + (size_t)(1027 + o) * HW) + (size_t)b * 1024;
            float4 v[4];
            #pragma unroll
            for (int k = 0; k < 4; k++) v[k] = heat[tid + k*256];

            float bv = -INFINITY; int bi = 0x7fffffff;
            int base = b * 4096;
            #pragma unroll
            for (int k = 0; k < 4; k++) {
                float m = fmaxf(fmaxf(v[k].x, v[k].y), fmaxf(v[k].z, v[k].w));
                if (m > bv) {
                    bv = m;
                    int j = base + (tid + k*256) * 4;
                    if      (v[k].x == m) bi = j;
                    else if (v[k].y == m) bi = j + 1;
                    else if (v[k].z == m) bi = j + 2;
                    else                  bi = j + 3;
                }
            }
            #pragma unroll
            for (int s = 16; s > 0; s >>= 1) {
                float ov = __shfl_down_sync(0xffffffffu, bv, s);
                int   oi = __shfl_down_sync(0xffffffffu, bi, s);
                better(ov, oi, bv, bi);
            }
            if ((tid & 31) == 0) { s_av[tid >> 5] = bv; s_ai[tid >> 5] = bi; }
            __syncthreads();
            if (tid == 0) {
                float rv = s_av[0]; int ri = s_ai[0];
                #pragma unroll
                for (int w = 1; w < 8; w++) better(s_av[w], s_ai[w], rv, ri);
                g_pval[t] = rv; g_pidx[t] = ri;
            }
            __syncthreads();            // protect s_av/s_ai reuse on next tile
        } else if (t < T_ARG + T_SIZE) {
            // ---- size map tile: out = abs(int(f[1025:1027])) ----
            int ts = t - T_ARG;
            const float4* src = (const float4*)(f + (size_t)1025*HW) + (size_t)ts * 1024;
            float4*       dst = (float4*)(out + SIZE_BASE) + (size_t)ts * 1024;
            #pragma unroll
            for (int k = 0; k < 4; k++) {
                float4 v = src[tid + k*256];
                int a0 = (int)v.x; if (a0 < 0) a0 = -a0;
                int a1 = (int)v.y; if (a1 < 0) a1 = -a1;
                int a2 = (int)v.z; if (a2 < 0) a2 = -a2;
                int a3 = (int)v.w; if (a3 < 0) a3 = -a3;
                dst[tid + k*256] = make_float4((float)a0, (float)a1, (float)a2, (float)a3);
            }
        } else {
            // ---- zero-fill one tile of the final mask ----
            int tz = t - T_ARG - T_SIZE;
            float4* dst = (float4*)(out + FIN_BASE) + (size_t)tz * 1024;
            float4 z = make_float4(0.f, 0.f, 0.f, 0.f);
            #pragma unroll
            for (int k = 0; k < 4; k++) dst[tid + k*256] = z;
        }
    }

    // ================= grid barrier =================
    __threadfence();
    __syncthreads();
    if (tid == 0) {
        unsigned old = atomicAdd(&g_arrive, 1u);
        s_last = (old == NB - 1);
    }
    __syncthreads();

    if (s_last) {
        // ---- finalize: reduce 640 partials -> boxes (8 warps, organs round-robin) ----
        int w = tid >> 5, lane = tid & 31;
        for (int o = w; o < NORG; o += 8) {
            float bv = g_pval[o*NPART + lane];
            int   bi = g_pidx[o*NPART + lane];
            better(g_pval[o*NPART + lane + 32], g_pidx[o*NPART + lane + 32], bv, bi);
            #pragma unroll
            for (int s = 16; s > 0; s >>= 1) {
                float ov = __shfl_down_sync(0xffffffffu, bv, s);
                int   oi = __shfl_down_sync(0xffffffffu, bi, s);
                better(ov, oi, bv, bi);
            }
            if (lane == 0) {
                int idx = bi;
                int py = idx / WW, px = idx % WW;
                int v0 = (int)f[(size_t)1025*HW + idx]; if (v0 < 0) v0 = -v0;
                int v1 = (int)f[(size_t)1026*HW + idx]; if (v1 < 0) v1 = -v1;
                int sh = v0 > 1 ? v0 : 1;
                int sw = v1 > 1 ? v1 : 1;
                g_box[o] = make_int4(py - sh/2, px - sw/2, sh, sw);
                g_idx[o] = idx;
                out[CEN_BASE + o*2 + 0] = (float)px;
                out[CEN_BASE + o*2 + 1] = (float)py;
            }
        }
        __syncthreads();
        if (tid == 0) {
            g_arrive = 0;                  // reset for next graph replay
            __threadfence();
            atomicAdd(&g_release, 1u);     // release waiters
        }
        __syncthreads();
    } else {
        if (tid == 0) {
            while (*(volatile unsigned*)&g_release == s_snap) __nanosleep(64);
        }
        __syncthreads();
        __threadfence();                   // acquire: make g_box/g_idx visible
    }

    // ================= Phase B: paint box interiors only =================
    for (int o = 0; o < NORG; o++) {
        int4 box = g_box[o];
        int idx  = g_idx[o];
        int r0 = box.x, c0 = box.y, sh = box.z, sw = box.w;
        int rlo = r0 > 0 ? r0 : 0;
        int rhi = (r0 + sh) < HH ? (r0 + sh) : HH;
        int clo = c0 > 0 ? c0 : 0;
        int chi = (c0 + sw) < WW ? (c0 + sw) : WW;
        int nrows = rhi - rlo;
        if (bid < nrows) {                               // uniform per block
            // load this organ's 32x32 shape logits straight from features
            #pragma unroll
            for (int i = tid; i < SS*SS; i += 256)
                s_shape[i] = f[(size_t)(1 + i)*HW + idx];
            __syncthreads();

            float inv_sh = (float)SS / (float)sh;
            float inv_sw = (float)SS / (float)sw;
            for (int r = rlo + bid; r < rhi; r += NB) {
                float sy = ((float)(r - r0) + 0.5f) * inv_sh - 0.5f;
                sy = fminf(fmaxf(sy, 0.0f), (float)(SS - 1));
                int y0 = (int)floorf(sy);
                int y1 = min(y0 + 1, SS - 1);
                float wy = sy - (float)y0;
                const float* sr0 = s_shape + y0*SS;
                const float* sr1 = s_shape + y1*SS;
                float* orow = out + FIN_BASE + (size_t)o*HW + (size_t)r*WW;
                const float* salrow = f + (size_t)r*WW;
                for (int c = clo + tid; c < chi; c += 256) {
                    float sx = ((float)(c - c0) + 0.5f) * inv_sw - 0.5f;
                    sx = fminf(fmaxf(sx, 0.0f), (float)(SS - 1));
                    int x0 = (int)floorf(sx);
                    int x1 = min(x0 + 1, SS - 1);
                    float wx = sx - (float)x0;
                    float top = (1.0f - wx)*sr0[x0] + wx*sr0[x1];
                    float bot = (1.0f - wx)*sr1[x0] + wx*sr1[x1];
                    float loc = (1.0f - wy)*top + wy*bot;
                    orow[c] = sigmoidf_(loc) * sigmoidf_(salrow[c]);
                }
            }
            __syncthreads();                             // protect s_shape reuse
        }
    }
}

extern "C" void kernel_launch(void* const* d_in, const int* in_sizes, int n_in,
                              void* d_out, int out_size) {
    const float* f = (const float*)d_in[0];
    float* out = (float*)d_out;
    (void)in_sizes; (void)n_in; (void)out_size;
    fused_all<<<NB, 256>>>(f, out);
}

// round 7
// speedup vs baseline: 2.2408x; 2.2408x over previous
#include <cuda_runtime.h>
#include <math.h>

#define HH 512
#define WW 512
#define HW (512*512)
#define NORG 10
#define SS 32
#define NPART 128                 // chunks per organ in stage 1
#define CHUNK (HW/NPART)          // 2048 floats

// Output layout (flattened reference tuple, fp32):
//   [0, 2*HW)            size map  = abs(int32(features[1025:1027]))
//   [2*HW, 2*HW+20)      centers   = (px, py) per organ
//   [2*HW+20, +10*HW)    final mask
#define SIZE_BASE 0
#define CEN_BASE  (2*HW)
#define FIN_BASE  (2*HW + 2*NORG)

// K2 grid: 10*512 row-tasks + 256 size-map tiles
#define T_ROWS (NORG*HH)          // 5120
#define T_SIZE 256                // 2*HW / 2048
#define NB2 (T_ROWS + T_SIZE)

// ---- scratch (no allocations allowed) ----
__device__ float g_pval[NORG*NPART];
__device__ int   g_pidx[NORG*NPART];

__device__ __forceinline__ void better(float v, int i, float& bv, int& bi) {
    if (v > bv || (v == bv && i < bi)) { bv = v; bi = i; }
}
__device__ __forceinline__ float sigmoidf_(float x) {
    return 1.0f / (1.0f + __expf(-x));
}

// ---------------- Kernel 1: argmax partials over heat ----------------
// 1280 blocks x 256 threads, 2 float4 per thread (batched before compares).
__global__ void argmax_stage1(const float* __restrict__ f) {
    int o = blockIdx.x >> 7;          // / NPART
    int b = blockIdx.x & 127;         // % NPART
    const float4* heat = (const float4*)(f + (size_t)(1027 + o) * HW) + (size_t)b * (CHUNK/4);
    int tid = threadIdx.x;

    float4 v[2];
    v[0] = heat[tid];
    v[1] = heat[tid + 256];

    float bv = -INFINITY; int bi = 0x7fffffff;
    int base = b * CHUNK;
    #pragma unroll
    for (int k = 0; k < 2; k++) {
        float m = fmaxf(fmaxf(v[k].x, v[k].y), fmaxf(v[k].z, v[k].w));
        if (m > bv) {
            bv = m;
            int j = base + (tid + k*256) * 4;
            if      (v[k].x == m) bi = j;
            else if (v[k].y == m) bi = j + 1;
            else if (v[k].z == m) bi = j + 2;
            else                  bi = j + 3;
        }
    }
    #pragma unroll
    for (int s = 16; s > 0; s >>= 1) {
        float ov = __shfl_down_sync(0xffffffffu, bv, s);
        int   oi = __shfl_down_sync(0xffffffffu, bi, s);
        better(ov, oi, bv, bi);
    }
    __shared__ float sv[8];
    __shared__ int   si[8];
    if ((tid & 31) == 0) { sv[tid >> 5] = bv; si[tid >> 5] = bi; }
    __syncthreads();
    if (tid == 0) {
        #pragma unroll
        for (int w = 1; w < 8; w++) better(sv[w], si[w], sv[0], si[0]);
        g_pval[blockIdx.x] = sv[0];
        g_pidx[blockIdx.x] = si[0];
    }
}

// ---------------- Kernel 2: everything else, flat grid, 128 threads ----------------
// bid <  T_ROWS : (organ, row) task — redundant 128-partial reduce, then write row
// bid >= T_ROWS : size-map tile (2048 floats)
__global__ void fused_out(const float* __restrict__ f, float* __restrict__ out) {
    int bid = blockIdx.x;
    int tid = threadIdx.x;

    if (bid >= T_ROWS) {
        int ts = bid - T_ROWS;
        const float4* src = (const float4*)(f + (size_t)1025*HW) + (size_t)ts * (CHUNK/4);
        float4*       dst = (float4*)(out + SIZE_BASE) + (size_t)ts * (CHUNK/4);
        #pragma unroll
        for (int k = 0; k < 4; k++) {
            float4 v = src[tid + k*128];
            int a0 = (int)v.x; if (a0 < 0) a0 = -a0;
            int a1 = (int)v.y; if (a1 < 0) a1 = -a1;
            int a2 = (int)v.z; if (a2 < 0) a2 = -a2;
            int a3 = (int)v.w; if (a3 < 0) a3 = -a3;
            dst[tid + k*128] = make_float4((float)a0, (float)a1, (float)a2, (float)a3);
        }
        return;
    }

    int o = bid >> 9;          // / HH
    int r = bid & 511;         // % HH

    // ---- per-block redundant argmax finish: 128 partials (L2-hot, 1 KB) ----
    __shared__ float s_wv[4];
    __shared__ int   s_wi[4];
    __shared__ int   s_box[5];     // idx, r0, c0, sh, sw
    {
        float bv = g_pval[o*NPART + tid];
        int   bi = g_pidx[o*NPART + tid];
        #pragma unroll
        for (int s = 16; s > 0; s >>= 1) {
            float ov = __shfl_down_sync(0xffffffffu, bv, s);
            int   oi = __shfl_down_sync(0xffffffffu, bi, s);
            better(ov, oi, bv, bi);
        }
        if ((tid & 31) == 0) { s_wv[tid >> 5] = bv; s_wi[tid >> 5] = bi; }
    }
    __syncthreads();
    if (tid == 0) {
        float bv = s_wv[0]; int bi = s_wi[0];
        better(s_wv[1], s_wi[1], bv, bi);
        better(s_wv[2], s_wi[2], bv, bi);
        better(s_wv[3], s_wi[3], bv, bi);
        int idx = bi;
        int py = idx / WW, px = idx % WW;
        int v0 = (int)f[(size_t)1025*HW + idx]; if (v0 < 0) v0 = -v0;
        int v1 = (int)f[(size_t)1026*HW + idx]; if (v1 < 0) v1 = -v1;
        int sh = v0 > 1 ? v0 : 1;
        int sw = v1 > 1 ? v1 : 1;
        s_box[0] = idx;
        s_box[1] = py - sh/2;
        s_box[2] = px - sw/2;
        s_box[3] = sh;
        s_box[4] = sw;
        if (r == 0) {                         // one block per organ writes its center
            out[CEN_BASE + o*2 + 0] = (float)px;
            out[CEN_BASE + o*2 + 1] = (float)py;
        }
    }
    __syncthreads();

    int idx = s_box[0], r0 = s_box[1], c0 = s_box[2], sh = s_box[3], sw = s_box[4];
    float4* orow = (float4*)(out + FIN_BASE + (size_t)o*HW + (size_t)r*WW);

    if (r < r0 || r >= r0 + sh) {             // row misses box: pure zero row
        orow[tid] = make_float4(0.f, 0.f, 0.f, 0.f);
        return;
    }

    // ---- gather the two shape rows this output row interpolates between ----
    float sy = ((float)(r - r0) + 0.5f) * ((float)SS / (float)sh) - 0.5f;
    sy = fminf(fmaxf(sy, 0.0f), (float)(SS - 1));
    int y0 = (int)floorf(sy);
    int y1 = min(y0 + 1, SS - 1);
    float wy = sy - (float)y0;

    __shared__ float s_r0[SS];
    __shared__ float s_r1[SS];
    if (tid < SS)
        s_r0[tid] = f[(size_t)(1 + y0*SS + tid)*HW + idx];
    else if (tid < 2*SS)
        s_r1[tid - SS] = f[(size_t)(1 + y1*SS + (tid - SS))*HW + idx];
    __syncthreads();

    int cb = tid * 4;
    float res[4] = {0.f, 0.f, 0.f, 0.f};
    if (cb + 4 > c0 && cb < c0 + sw) {
        float inv_sw = (float)SS / (float)sw;
        #pragma unroll
        for (int j = 0; j < 4; j++) {
            int c = cb + j;
            if (c >= c0 && c < c0 + sw) {
                float sx = ((float)(c - c0) + 0.5f) * inv_sw - 0.5f;
                sx = fminf(fmaxf(sx, 0.0f), (float)(SS - 1));
                int x0 = (int)floorf(sx);
                int x1 = min(x0 + 1, SS - 1);
                float wx = sx - (float)x0;
                float top = (1.0f - wx)*s_r0[x0] + wx*s_r0[x1];
                float bot = (1.0f - wx)*s_r1[x0] + wx*s_r1[x1];
                float loc = (1.0f - wy)*top + wy*bot;
                float sal = f[(size_t)r*WW + c];    // channel 0
                res[j] = sigmoidf_(loc) * sigmoidf_(sal);
            }
        }
    }
    orow[tid] = make_float4(res[0], res[1], res[2], res[3]);
}

extern "C" void kernel_launch(void* const* d_in, const int* in_sizes, int n_in,
                              void* d_out, int out_size) {
    const float* f = (const float*)d_in[0];
    float* out = (float*)d_out;
    (void)in_sizes; (void)n_in; (void)out_size;

    argmax_stage1<<<NORG*NPART, 256>>>(f);
    fused_out<<<NB2, 128>>>(f, out);
}